// round 12
// baseline (speedup 1.0000x reference)
#include <cuda_runtime.h>
#include <cuda_bf16.h>
#include <math.h>
#include <stdint.h>

// ---------------------------------------------------------------------------
// Problem constants
// ---------------------------------------------------------------------------
#define WS   7
#define NTOK 49
#define DIM  256
#define NH   8
#define DH   32
#define NB   2048
#define NW   64
#define ROWS (NB * NTOK)   // 100352
#define QKV_COLS (3 * DIM) // 768

// Scratch (static device globals)
__device__ float g_qkv[(size_t)ROWS * QKV_COLS];
__device__ float g_att[(size_t)ROWS * DIM];
__device__ float g_xr[(size_t)ROWS * DIM];
__device__ float g_wqkv[QKV_COLS * DIM];
__device__ float g_wproj[DIM * DIM];
__device__ float g_bias[NH * NW * NTOK * NTOK];

__device__ __forceinline__ float to_tf32(float x) {
    asm("cvt.rna.tf32.f32 %0, %1;" : "=f"(x) : "f"(x));
    return x;
}

// ---------------------------------------------------------------------------
// Prep kernels
// ---------------------------------------------------------------------------
#define NX4 (ROWS * DIM / 4)
#define NQ4 (QKV_COLS * DIM / 4)
#define NP4 (DIM * DIM / 4)

__global__ void round_all_kernel(const float* __restrict__ x,
                                 const float* __restrict__ qw,
                                 const float* __restrict__ pw,
                                 float* __restrict__ xr,
                                 float* __restrict__ wq,
                                 float* __restrict__ wp) {
    int i = blockIdx.x * blockDim.x + threadIdx.x;
    const float4* src;
    float4* dst;
    int j;
    if (i < NX4)            { src = (const float4*)x;  dst = (float4*)xr; j = i; }
    else if (i < NX4 + NQ4) { src = (const float4*)qw; dst = (float4*)wq; j = i - NX4; }
    else if (i < NX4 + NQ4 + NP4) { src = (const float4*)pw; dst = (float4*)wp; j = i - NX4 - NQ4; }
    else return;
    float4 v = src[j];
    v.x = to_tf32(v.x); v.y = to_tf32(v.y);
    v.z = to_tf32(v.z); v.w = to_tf32(v.w);
    dst[j] = v;
}

__global__ void bias_comb_kernel(const float* __restrict__ rpb_table,
                                 const int* __restrict__ rel_index,
                                 const float* __restrict__ mask,
                                 float* __restrict__ bias) {
    int idx = blockIdx.x * blockDim.x + threadIdx.x;
    const int total = NH * NW * NTOK * NTOK;
    if (idx >= total) return;
    int p = idx % (NTOK * NTOK);
    int hw = idx / (NTOK * NTOK);
    int w = hw % NW;
    int h = hw / NW;
    bias[idx] = rpb_table[rel_index[p] * NH + h] + mask[w * NTOK * NTOK + p];
}

// ---------------------------------------------------------------------------
// tf32 tensor-core GEMM: C[r,c] = sum_k A[r,k] * W[c,k] + bias[c]
// Block 128x256, BK=32, 8 warps each 64x64 (96B fragment traffic per mma,
// vs 160B for 64x32), 256 threads, 2-stage cp.async double buffer (proven
// r3 structure). Requires M%128==0, Nc%256==0, K%32==0.
// ---------------------------------------------------------------------------
#define GBM 128
#define GBN 256
#define GBK 32
#define TSTR 36
#define ASZ (GBM * TSTR)                  // 4608 floats
#define BSZ (GBN * TSTR)                  // 9216 floats
#define STAGE_FLOATS (ASZ + BSZ)          // 13824
#define GEMM_SMEM (2 * STAGE_FLOATS * 4)  // 110592 bytes

__device__ __forceinline__ void cp_async16(uint32_t saddr, const void* g) {
    asm volatile("cp.async.cg.shared.global [%0], [%1], 16;\n"
                 :: "r"(saddr), "l"(g));
}
__device__ __forceinline__ void cp_commit() {
    asm volatile("cp.async.commit_group;\n");
}
__device__ __forceinline__ void cp_wait1() {
    asm volatile("cp.async.wait_group 1;\n");
}
__device__ __forceinline__ void cp_wait0() {
    asm volatile("cp.async.wait_group 0;\n");
}

__device__ __forceinline__ void mma_tf32(float d[4], const uint32_t a[4],
                                         const uint32_t b[2]) {
    asm volatile(
        "mma.sync.aligned.m16n8k8.row.col.f32.tf32.tf32.f32 "
        "{%0,%1,%2,%3}, {%4,%5,%6,%7}, {%8,%9}, {%0,%1,%2,%3};\n"
        : "+f"(d[0]), "+f"(d[1]), "+f"(d[2]), "+f"(d[3])
        : "r"(a[0]), "r"(a[1]), "r"(a[2]), "r"(a[3]), "r"(b[0]), "r"(b[1]));
}

__global__ __launch_bounds__(256, 1)
void tf32_gemm_bias_kernel(const float* __restrict__ A,
                           const float* __restrict__ W,
                           const float* __restrict__ bias,
                           float* __restrict__ C,
                           int M, int Nc, int K) {
    extern __shared__ float sm[];

    const int tx = threadIdx.x;
    const int lane = tx & 31;
    const int warp = tx >> 5;
    const int wm = (warp & 1) * 64;       // 2 m-warps
    const int wn = (warp >> 1) * 64;      // 4 n-warps
    const int rowBlk = blockIdx.y * GBM;
    const int colBlk = blockIdx.x * GBN;

    const int lr = tx >> 3;               // 0..31
    const int lc4 = (tx & 7) * 4;

    float acc[4][8][4];
#pragma unroll
    for (int mt = 0; mt < 4; mt++)
#pragma unroll
        for (int nt = 0; nt < 8; nt++)
#pragma unroll
            for (int e = 0; e < 4; e++) acc[mt][nt][e] = 0.0f;

    const int ar = lane >> 2;
    const int ac = lane & 3;
    const int nk = K >> 5;

    auto load_tile = [&](int kt, int buf) {
        float* ad = sm + buf * STAGE_FLOATS;
        float* bd = ad + ASZ;
#pragma unroll
        for (int i = 0; i < 4; i++) {     // A: 128 rows
            int r = lr + i * 32;
            cp_async16((uint32_t)__cvta_generic_to_shared(ad + r * TSTR + lc4),
                       &A[(size_t)(rowBlk + r) * K + (kt << 5) + lc4]);
        }
#pragma unroll
        for (int i = 0; i < 8; i++) {     // B: 256 rows
            int r = lr + i * 32;
            cp_async16((uint32_t)__cvta_generic_to_shared(bd + r * TSTR + lc4),
                       &W[(size_t)(colBlk + r) * K + (kt << 5) + lc4]);
        }
        cp_commit();
    };

    load_tile(0, 0);

    for (int t = 0; t < nk; t++) {
        if (t + 1 < nk) { load_tile(t + 1, (t + 1) & 1); cp_wait1(); }
        else            { cp_wait0(); }
        __syncthreads();

        const float* a = sm + (t & 1) * STAGE_FLOATS;
        const float* b = a + ASZ;
#pragma unroll
        for (int kk = 0; kk < GBK; kk += 8) {
            uint32_t af[4][4];
#pragma unroll
            for (int mt = 0; mt < 4; mt++) {
                int mb = wm + mt * 16;
                af[mt][0] = __float_as_uint(a[(mb + ar) * TSTR + kk + ac]);
                af[mt][1] = __float_as_uint(a[(mb + ar + 8) * TSTR + kk + ac]);
                af[mt][2] = __float_as_uint(a[(mb + ar) * TSTR + kk + ac + 4]);
                af[mt][3] = __float_as_uint(a[(mb + ar + 8) * TSTR + kk + ac + 4]);
            }
            uint32_t bf[8][2];
#pragma unroll
            for (int nt = 0; nt < 8; nt++) {
                int nb2 = wn + nt * 8 + ar;
                bf[nt][0] = __float_as_uint(b[nb2 * TSTR + kk + ac]);
                bf[nt][1] = __float_as_uint(b[nb2 * TSTR + kk + ac + 4]);
            }
#pragma unroll
            for (int mt = 0; mt < 4; mt++)
#pragma unroll
                for (int nt = 0; nt < 8; nt++)
                    mma_tf32(acc[mt][nt], af[mt], bf[nt]);
        }
        __syncthreads();
    }

    const int cr = lane >> 2;
    const int cc = (lane & 3) * 2;
#pragma unroll
    for (int mt = 0; mt < 4; mt++) {
#pragma unroll
        for (int nt = 0; nt < 8; nt++) {
            int row = rowBlk + wm + mt * 16 + cr;
            int col = colBlk + wn + nt * 8 + cc;
            float b0 = bias[col], b1 = bias[col + 1];
            float2 v0 = make_float2(acc[mt][nt][0] + b0, acc[mt][nt][1] + b1);
            float2 v1 = make_float2(acc[mt][nt][2] + b0, acc[mt][nt][3] + b1);
            *reinterpret_cast<float2*>(&C[(size_t)row * Nc + col]) = v0;
            *reinterpret_cast<float2*>(&C[(size_t)(row + 8) * Nc + col]) = v1;
        }
    }
}

// ---------------------------------------------------------------------------
// Tensor-core window attention v3 (round-11 passing kernel, unchanged)
// ---------------------------------------------------------------------------
#define QKSTR 36
#define PSTR  60
#define VSTR  68
#define QS_OFF 0
#define KS_OFF (64 * QKSTR)
#define VT_OFF (KS_OFF + 64 * QKSTR)
#define PS_OFF (VT_OFF + DH * VSTR)
#define GRP_FLOATS (PS_OFF + 64 * PSTR)
#define ATT_SMEM (2 * GRP_FLOATS * 4)

__global__ __launch_bounds__(256)
void window_attn_mma3_kernel(const float* __restrict__ qkv,
                             const float* __restrict__ bias_comb,
                             float* __restrict__ att_out) {
    extern __shared__ float smf[];

    const int b = blockIdx.x;
    const int tid = threadIdx.x;
    const int lane = tid & 31;
    const int warp = tid >> 5;
    const int group = warp >> 2;
    const int wg = warp & 3;
    const int t128 = tid & 127;
    const int ar = lane >> 2;
    const int ac = lane & 3;
    const int m0 = wg * 16;
    const size_t row_base = (size_t)b * NTOK;
    const float scale = 0.17677669529663687f;

    float* qs = smf + group * GRP_FLOATS + QS_OFF;
    float* ks = smf + group * GRP_FLOATS + KS_OFF;
    float* vt = smf + group * GRP_FLOATS + VT_OFF;
    float* ps = smf + group * GRP_FLOATS + PS_OFF;

    for (int p = t128; p < 15 * QKSTR; p += 128) {
        qs[49 * QKSTR + p] = 0.0f;
        ks[49 * QKSTR + p] = 0.0f;
    }

    const int br0 = (m0 + ar < NTOK) ? m0 + ar : NTOK - 1;
    const int br1 = (m0 + ar + 8 < NTOK) ? m0 + ar + 8 : NTOK - 1;

    for (int hh = 0; hh < 4; hh++) {
        const int h = hh * 2 + group;
        const int hcol = h * DH;

        for (int p = t128; p < NTOK * 8; p += 128) {
            int n = p >> 3, d0 = (p & 7) * 4;
            const float* base = qkv + (row_base + n) * QKV_COLS + hcol + d0;
            float4 q = *reinterpret_cast<const float4*>(base);
            float4 k = *reinterpret_cast<const float4*>(base + DIM);
            float* qd = &qs[n * QKSTR + d0];
            float* kd = &ks[n * QKSTR + d0];
            qd[0] = to_tf32(q.x * scale); qd[1] = to_tf32(q.y * scale);
            qd[2] = to_tf32(q.z * scale); qd[3] = to_tf32(q.w * scale);
            kd[0] = to_tf32(k.x); kd[1] = to_tf32(k.y);
            kd[2] = to_tf32(k.z); kd[3] = to_tf32(k.w);
        }
#pragma unroll
        for (int jj = 0; jj < 14; jj++) {
            int j = wg * 14 + jj;
            float v = (j < NTOK)
                ? qkv[(row_base + j) * QKV_COLS + hcol + 2 * DIM + lane] : 0.0f;
            vt[lane * VSTR + j] = to_tf32(v);
        }
        asm volatile("bar.sync %0, 128;" :: "r"(group + 1) : "memory");

        float acc[8][4];
#pragma unroll
        for (int nt = 0; nt < 8; nt++)
#pragma unroll
            for (int e = 0; e < 4; e++) acc[nt][e] = 0.0f;
#pragma unroll
        for (int kt = 0; kt < 4; kt++) {
            int kk = kt * 8;
            uint32_t af[4];
            af[0] = __float_as_uint(qs[(m0 + ar) * QKSTR + kk + ac]);
            af[1] = __float_as_uint(qs[(m0 + ar + 8) * QKSTR + kk + ac]);
            af[2] = __float_as_uint(qs[(m0 + ar) * QKSTR + kk + ac + 4]);
            af[3] = __float_as_uint(qs[(m0 + ar + 8) * QKSTR + kk + ac + 4]);
#pragma unroll
            for (int nt = 0; nt < 8; nt++) {
                uint32_t bf[2];
                int nb = nt * 8 + ar;
                bf[0] = __float_as_uint(ks[nb * QKSTR + kk + ac]);
                bf[1] = __float_as_uint(ks[nb * QKSTR + kk + ac + 4]);
                mma_tf32(acc[nt], af, bf);
            }
        }

        {
            const float* bc = bias_comb
                + (size_t)(h * NW + (b & (NW - 1))) * NTOK * NTOK;
            float m0r = -1e30f, m1r = -1e30f;
#pragma unroll
            for (int nt = 0; nt < 8; nt++) {
                int c0 = nt * 8 + 2 * ac, c1 = c0 + 1;
                acc[nt][0] = (c0 < NTOK) ? acc[nt][0] + bc[br0 * NTOK + c0] : -1e30f;
                acc[nt][1] = (c1 < NTOK) ? acc[nt][1] + bc[br0 * NTOK + c1] : -1e30f;
                acc[nt][2] = (c0 < NTOK) ? acc[nt][2] + bc[br1 * NTOK + c0] : -1e30f;
                acc[nt][3] = (c1 < NTOK) ? acc[nt][3] + bc[br1 * NTOK + c1] : -1e30f;
                m0r = fmaxf(m0r, fmaxf(acc[nt][0], acc[nt][1]));
                m1r = fmaxf(m1r, fmaxf(acc[nt][2], acc[nt][3]));
            }
            m0r = fmaxf(m0r, __shfl_xor_sync(~0u, m0r, 1));
            m0r = fmaxf(m0r, __shfl_xor_sync(~0u, m0r, 2));
            m1r = fmaxf(m1r, __shfl_xor_sync(~0u, m1r, 1));
            m1r = fmaxf(m1r, __shfl_xor_sync(~0u, m1r, 2));
            float s0 = 0.0f, s1 = 0.0f;
#pragma unroll
            for (int nt = 0; nt < 8; nt++) {
                acc[nt][0] = __expf(acc[nt][0] - m0r); s0 += acc[nt][0];
                acc[nt][1] = __expf(acc[nt][1] - m0r); s0 += acc[nt][1];
                acc[nt][2] = __expf(acc[nt][2] - m1r); s1 += acc[nt][2];
                acc[nt][3] = __expf(acc[nt][3] - m1r); s1 += acc[nt][3];
            }
            s0 += __shfl_xor_sync(~0u, s0, 1); s0 += __shfl_xor_sync(~0u, s0, 2);
            s1 += __shfl_xor_sync(~0u, s1, 1); s1 += __shfl_xor_sync(~0u, s1, 2);
            float i0 = __frcp_rn(s0), i1 = __frcp_rn(s1);
#pragma unroll
            for (int nt = 0; nt < 7; nt++) {
                int c0 = nt * 8 + 2 * ac;
                *reinterpret_cast<float2*>(&ps[(m0 + ar) * PSTR + c0]) =
                    make_float2(to_tf32(acc[nt][0] * i0), to_tf32(acc[nt][1] * i0));
                *reinterpret_cast<float2*>(&ps[(m0 + ar + 8) * PSTR + c0]) =
                    make_float2(to_tf32(acc[nt][2] * i1), to_tf32(acc[nt][3] * i1));
            }
        }
        __syncwarp();

        {
            float po[4][4];
#pragma unroll
            for (int nt = 0; nt < 4; nt++)
#pragma unroll
                for (int e = 0; e < 4; e++) po[nt][e] = 0.0f;
#pragma unroll
            for (int kt = 0; kt < 7; kt++) {
                int kk = kt * 8;
                uint32_t af[4];
                af[0] = __float_as_uint(ps[(m0 + ar) * PSTR + kk + ac]);
                af[1] = __float_as_uint(ps[(m0 + ar + 8) * PSTR + kk + ac]);
                af[2] = __float_as_uint(ps[(m0 + ar) * PSTR + kk + ac + 4]);
                af[3] = __float_as_uint(ps[(m0 + ar + 8) * PSTR + kk + ac + 4]);
#pragma unroll
                for (int nt = 0; nt < 4; nt++) {
                    uint32_t bf[2];
                    int nb = nt * 8 + ar;
                    bf[0] = __float_as_uint(vt[nb * VSTR + kk + ac]);
                    bf[1] = __float_as_uint(vt[nb * VSTR + kk + ac + 4]);
                    mma_tf32(po[nt], af, bf);
                }
            }
            int i0 = m0 + ar;
#pragma unroll
            for (int nt = 0; nt < 4; nt++) {
                int col = hcol + nt * 8 + 2 * ac;
                if (i0 < NTOK)
                    *reinterpret_cast<float2*>(
                        &att_out[(row_base + i0) * DIM + col]) =
                        make_float2(to_tf32(po[nt][0]), to_tf32(po[nt][1]));
                if (i0 + 8 < NTOK)
                    *reinterpret_cast<float2*>(
                        &att_out[(row_base + i0 + 8) * DIM + col]) =
                        make_float2(to_tf32(po[nt][2]), to_tf32(po[nt][3]));
            }
        }

        asm volatile("bar.sync %0, 128;" :: "r"(group + 1) : "memory");
    }
}

// ---------------------------------------------------------------------------
// Launch
// Inputs: 0:x 1:mask 2:qkv_w 3:qkv_b 4:proj_w 5:proj_b 6:rpb_table 7:rel_index
// ---------------------------------------------------------------------------
extern "C" void kernel_launch(void* const* d_in, const int* in_sizes, int n_in,
                              void* d_out, int out_size) {
    const float* x         = (const float*)d_in[0];
    const float* mask      = (const float*)d_in[1];
    const float* qkv_w     = (const float*)d_in[2];
    const float* qkv_b     = (const float*)d_in[3];
    const float* proj_w    = (const float*)d_in[4];
    const float* proj_b    = (const float*)d_in[5];
    const float* rpb_table = (const float*)d_in[6];
    const int*   rel_index = (const int*)d_in[7];
    float* out = (float*)d_out;

    float *qkv, *att, *xr, *wqkv, *wproj, *biasc;
    cudaGetSymbolAddress((void**)&qkv,   g_qkv);
    cudaGetSymbolAddress((void**)&att,   g_att);
    cudaGetSymbolAddress((void**)&xr,    g_xr);
    cudaGetSymbolAddress((void**)&wqkv,  g_wqkv);
    cudaGetSymbolAddress((void**)&wproj, g_wproj);
    cudaGetSymbolAddress((void**)&biasc, g_bias);

    static bool attr_done = false;
    if (!attr_done) {
        cudaFuncSetAttribute(tf32_gemm_bias_kernel,
                             cudaFuncAttributeMaxDynamicSharedMemorySize,
                             GEMM_SMEM);
        cudaFuncSetAttribute(window_attn_mma3_kernel,
                             cudaFuncAttributeMaxDynamicSharedMemorySize,
                             ATT_SMEM);
        attr_done = true;
    }

    // launches 0,1: prep
    {
        int n4 = NX4 + NQ4 + NP4;
        round_all_kernel<<<(n4 + 255) / 256, 256>>>(x, qkv_w, proj_w, xr, wqkv, wproj);
        int nb = NH * NW * NTOK * NTOK;
        bias_comb_kernel<<<(nb + 255) / 256, 256>>>(rpb_table, rel_index, mask, biasc);
    }

    // launch 2: QKV projection (100352,256)@(768,256)^T
    tf32_gemm_bias_kernel<<<dim3(QKV_COLS / GBN, ROWS / GBM), 256, GEMM_SMEM>>>(
        xr, wqkv, qkv_b, qkv, ROWS, QKV_COLS, DIM);

    // launch 3: attention (ncu capture slot)
    window_attn_mma3_kernel<<<NB, 256, ATT_SMEM>>>(qkv, biasc, att);

    // launch 4: output projection (100352,256)@(256,256)^T
    tf32_gemm_bias_kernel<<<dim3(DIM / GBN, ROWS / GBM), 256, GEMM_SMEM>>>(
        att, wproj, proj_b, out, ROWS, DIM, DIM);
}

// round 14
// speedup vs baseline: 1.6071x; 1.6071x over previous
#include <cuda_runtime.h>
#include <cuda_bf16.h>
#include <math.h>
#include <stdint.h>

// ---------------------------------------------------------------------------
// Problem constants
// ---------------------------------------------------------------------------
#define WS   7
#define NTOK 49
#define DIM  256
#define NH   8
#define DH   32
#define NB   2048
#define NW   64
#define ROWS (NB * NTOK)   // 100352
#define QKV_COLS (3 * DIM) // 768

// Scratch (static device globals)
__device__ float g_qkv[(size_t)ROWS * QKV_COLS];
__device__ float g_att[(size_t)ROWS * DIM];
__device__ float g_xr[(size_t)ROWS * DIM];
__device__ float g_wqkv[QKV_COLS * DIM];
__device__ float g_wproj[DIM * DIM];
__device__ float g_bias[NH * NW * NTOK * NTOK];

__device__ __forceinline__ float to_tf32(float x) {
    asm("cvt.rna.tf32.f32 %0, %1;" : "=f"(x) : "f"(x));
    return x;
}

// ---------------------------------------------------------------------------
// Prep kernels
// ---------------------------------------------------------------------------
#define NX4 (ROWS * DIM / 4)
#define NQ4 (QKV_COLS * DIM / 4)
#define NP4 (DIM * DIM / 4)

__global__ void round_all_kernel(const float* __restrict__ x,
                                 const float* __restrict__ qw,
                                 const float* __restrict__ pw,
                                 float* __restrict__ xr,
                                 float* __restrict__ wq,
                                 float* __restrict__ wp) {
    int i = blockIdx.x * blockDim.x + threadIdx.x;
    const float4* src;
    float4* dst;
    int j;
    if (i < NX4)            { src = (const float4*)x;  dst = (float4*)xr; j = i; }
    else if (i < NX4 + NQ4) { src = (const float4*)qw; dst = (float4*)wq; j = i - NX4; }
    else if (i < NX4 + NQ4 + NP4) { src = (const float4*)pw; dst = (float4*)wp; j = i - NX4 - NQ4; }
    else return;
    float4 v = src[j];
    v.x = to_tf32(v.x); v.y = to_tf32(v.y);
    v.z = to_tf32(v.z); v.w = to_tf32(v.w);
    dst[j] = v;
}

__global__ void bias_comb_kernel(const float* __restrict__ rpb_table,
                                 const int* __restrict__ rel_index,
                                 const float* __restrict__ mask,
                                 float* __restrict__ bias) {
    int idx = blockIdx.x * blockDim.x + threadIdx.x;
    const int total = NH * NW * NTOK * NTOK;
    if (idx >= total) return;
    int p = idx % (NTOK * NTOK);
    int hw = idx / (NTOK * NTOK);
    int w = hw % NW;
    int h = hw / NW;
    bias[idx] = rpb_table[rel_index[p] * NH + h] + mask[w * NTOK * NTOK + p];
}

// ---------------------------------------------------------------------------
// tf32 tensor-core GEMM — EXACT round-11 config (measured QKV = 268us):
// Block 128x128, BK=32, 8 warps each 64x32, 256 threads, 3-stage cp.async
// with corrected wait discipline.
// ---------------------------------------------------------------------------
#define GBM 128
#define GBN 128
#define GBK 32
#define TSTR 36
#define ASZ (GBM * TSTR)
#define BSZ (GBN * TSTR)
#define STAGE_FLOATS (ASZ + BSZ)
#define GEMM_SMEM (3 * STAGE_FLOATS * 4)     // 110592 bytes

__device__ __forceinline__ void cp_async16(uint32_t saddr, const void* g) {
    asm volatile("cp.async.cg.shared.global [%0], [%1], 16;\n"
                 :: "r"(saddr), "l"(g));
}
__device__ __forceinline__ void cp_commit() {
    asm volatile("cp.async.commit_group;\n");
}
__device__ __forceinline__ void cp_wait1() {
    asm volatile("cp.async.wait_group 1;\n");
}
__device__ __forceinline__ void cp_wait0() {
    asm volatile("cp.async.wait_group 0;\n");
}

__device__ __forceinline__ void mma_tf32(float d[4], const uint32_t a[4],
                                         const uint32_t b[2]) {
    asm volatile(
        "mma.sync.aligned.m16n8k8.row.col.f32.tf32.tf32.f32 "
        "{%0,%1,%2,%3}, {%4,%5,%6,%7}, {%8,%9}, {%0,%1,%2,%3};\n"
        : "+f"(d[0]), "+f"(d[1]), "+f"(d[2]), "+f"(d[3])
        : "r"(a[0]), "r"(a[1]), "r"(a[2]), "r"(a[3]), "r"(b[0]), "r"(b[1]));
}

__global__ __launch_bounds__(256, 2)
void tf32_gemm_bias_kernel(const float* __restrict__ A,
                           const float* __restrict__ W,
                           const float* __restrict__ bias,
                           float* __restrict__ C,
                           int M, int Nc, int K) {
    extern __shared__ float sm[];

    const int tx = threadIdx.x;
    const int lane = tx & 31;
    const int warp = tx >> 5;
    const int wm = (warp & 1) * 64;
    const int wn = (warp >> 1) * 32;
    const int rowBlk = blockIdx.y * GBM;
    const int colBlk = blockIdx.x * GBN;

    const int lr = tx >> 3;             // 0..31
    const int lc4 = (tx & 7) * 4;

    float acc[4][4][4];
#pragma unroll
    for (int mt = 0; mt < 4; mt++)
#pragma unroll
        for (int nt = 0; nt < 4; nt++)
#pragma unroll
            for (int e = 0; e < 4; e++) acc[mt][nt][e] = 0.0f;

    const int ar = lane >> 2;
    const int ac = lane & 3;
    const int nk = K >> 5;

    auto load_tile = [&](int kt, int buf) {
        float* ad = sm + buf * STAGE_FLOATS;
        float* bd = ad + ASZ;
#pragma unroll
        for (int i = 0; i < 4; i++) {
            int r = lr + i * 32;
            cp_async16((uint32_t)__cvta_generic_to_shared(ad + r * TSTR + lc4),
                       &A[(size_t)(rowBlk + r) * K + (kt << 5) + lc4]);
            cp_async16((uint32_t)__cvta_generic_to_shared(bd + r * TSTR + lc4),
                       &W[(size_t)(colBlk + r) * K + (kt << 5) + lc4]);
        }
        cp_commit();
    };

    load_tile(0, 0);
    if (nk > 1) load_tile(1, 1);

    int buf = 0;
    for (int t = 0; t < nk; t++) {
        // pending groups here: tiles t, t+1 (t+2 not yet issued)
        if (t + 1 < nk) cp_wait1();
        else            cp_wait0();
        __syncthreads();
        if (t + 2 < nk) {
            int nb = buf + 2; if (nb >= 3) nb -= 3;
            load_tile(t + 2, nb);
        }

        const float* a = sm + buf * STAGE_FLOATS;
        const float* b = a + ASZ;
#pragma unroll
        for (int kk = 0; kk < GBK; kk += 8) {
            uint32_t af[4][4];
#pragma unroll
            for (int mt = 0; mt < 4; mt++) {
                int mb = wm + mt * 16;
                af[mt][0] = __float_as_uint(a[(mb + ar) * TSTR + kk + ac]);
                af[mt][1] = __float_as_uint(a[(mb + ar + 8) * TSTR + kk + ac]);
                af[mt][2] = __float_as_uint(a[(mb + ar) * TSTR + kk + ac + 4]);
                af[mt][3] = __float_as_uint(a[(mb + ar + 8) * TSTR + kk + ac + 4]);
            }
            uint32_t bf[4][2];
#pragma unroll
            for (int nt = 0; nt < 4; nt++) {
                int nb2 = wn + nt * 8 + ar;
                bf[nt][0] = __float_as_uint(b[nb2 * TSTR + kk + ac]);
                bf[nt][1] = __float_as_uint(b[nb2 * TSTR + kk + ac + 4]);
            }
#pragma unroll
            for (int mt = 0; mt < 4; mt++)
#pragma unroll
                for (int nt = 0; nt < 4; nt++)
                    mma_tf32(acc[mt][nt], af[mt], bf[nt]);
        }
        if (++buf >= 3) buf = 0;
    }

    const int cr = lane >> 2;
    const int cc = (lane & 3) * 2;
#pragma unroll
    for (int mt = 0; mt < 4; mt++) {
#pragma unroll
        for (int nt = 0; nt < 4; nt++) {
            int row = rowBlk + wm + mt * 16 + cr;
            int col = colBlk + wn + nt * 8 + cc;
            float b0 = bias[col], b1 = bias[col + 1];
            float2 v0 = make_float2(acc[mt][nt][0] + b0, acc[mt][nt][1] + b1);
            float2 v1 = make_float2(acc[mt][nt][2] + b0, acc[mt][nt][3] + b1);
            *reinterpret_cast<float2*>(&C[(size_t)row * Nc + col]) = v0;
            *reinterpret_cast<float2*>(&C[(size_t)(row + 8) * Nc + col]) = v1;
        }
    }
}

// ---------------------------------------------------------------------------
// Tensor-core window attention v4: same structure as v3 but Ps ALIASES the
// Qs+Ks region (Ps is only written after all QK fragment reads, enforced by
// an extra group barrier). Per-group smem drops 10624 -> 6784 floats;
// ATT_SMEM 85KB -> 54.3KB => 4 CTAs/SM (was 2), occupancy cap 33% -> 67%.
// Layout per group: [Vt: 2176][union(Qs 2304 | Ps 3840) + Ks: 4608]
// ---------------------------------------------------------------------------
#define QKSTR 36
#define PSTR  60
#define VSTR  68
#define VT_OFF 0
#define QS_OFF (DH * VSTR)                  // 2176
#define KS_OFF (QS_OFF + 64 * QKSTR)        // 2176 + 2304 = 4480
#define PS_OFF QS_OFF                       // alias Qs (and start of Ks)
#define GRP_FLOATS (QS_OFF + 2 * 64 * QKSTR)  // 2176 + 4608 = 6784
#define ATT_SMEM (2 * GRP_FLOATS * 4)       // 54272 bytes

__global__ __launch_bounds__(256)
void window_attn_mma4_kernel(const float* __restrict__ qkv,
                             const float* __restrict__ bias_comb,
                             float* __restrict__ att_out) {
    extern __shared__ float smf[];

    const int b = blockIdx.x;
    const int tid = threadIdx.x;
    const int lane = tid & 31;
    const int warp = tid >> 5;
    const int group = warp >> 2;
    const int wg = warp & 3;
    const int t128 = tid & 127;
    const int ar = lane >> 2;
    const int ac = lane & 3;
    const int m0 = wg * 16;
    const size_t row_base = (size_t)b * NTOK;
    const float scale = 0.17677669529663687f;

    float* vt = smf + group * GRP_FLOATS + VT_OFF;
    float* qs = smf + group * GRP_FLOATS + QS_OFF;
    float* ks = smf + group * GRP_FLOATS + KS_OFF;
    float* ps = smf + group * GRP_FLOATS + PS_OFF;

    const int br0 = (m0 + ar < NTOK) ? m0 + ar : NTOK - 1;
    const int br1 = (m0 + ar + 8 < NTOK) ? m0 + ar + 8 : NTOK - 1;

    for (int hh = 0; hh < 4; hh++) {
        const int h = hh * 2 + group;
        const int hcol = h * DH;

        // ---- stage Q (scaled, tf32), K, pad rows zeroed every head
        // (Ps aliased over this region each iteration) ----
        for (int p = t128; p < 64 * 8; p += 128) {
            int n = p >> 3, d0 = (p & 7) * 4;
            float4 q, k;
            if (n < NTOK) {
                const float* base = qkv + (row_base + n) * QKV_COLS + hcol + d0;
                q = *reinterpret_cast<const float4*>(base);
                k = *reinterpret_cast<const float4*>(base + DIM);
                q.x *= scale; q.y *= scale; q.z *= scale; q.w *= scale;
            } else {
                q = make_float4(0.f, 0.f, 0.f, 0.f);
                k = q;
            }
            float* qd = &qs[n * QKSTR + d0];
            float* kd = &ks[n * QKSTR + d0];
            qd[0] = to_tf32(q.x); qd[1] = to_tf32(q.y);
            qd[2] = to_tf32(q.z); qd[3] = to_tf32(q.w);
            kd[0] = to_tf32(k.x); kd[1] = to_tf32(k.y);
            kd[2] = to_tf32(k.z); kd[3] = to_tf32(k.w);
        }
#pragma unroll
        for (int jj = 0; jj < 14; jj++) {
            int j = wg * 14 + jj;
            float v = (j < NTOK)
                ? qkv[(row_base + j) * QKV_COLS + hcol + 2 * DIM + lane] : 0.0f;
            vt[lane * VSTR + j] = to_tf32(v);
        }
        asm volatile("bar.sync %0, 128;" :: "r"(group + 1) : "memory");

        // ---- QK^T: warp rows m0..m0+15 x cols 0..63 ----
        float acc[8][4];
#pragma unroll
        for (int nt = 0; nt < 8; nt++)
#pragma unroll
            for (int e = 0; e < 4; e++) acc[nt][e] = 0.0f;
#pragma unroll
        for (int kt = 0; kt < 4; kt++) {
            int kk = kt * 8;
            uint32_t af[4];
            af[0] = __float_as_uint(qs[(m0 + ar) * QKSTR + kk + ac]);
            af[1] = __float_as_uint(qs[(m0 + ar + 8) * QKSTR + kk + ac]);
            af[2] = __float_as_uint(qs[(m0 + ar) * QKSTR + kk + ac + 4]);
            af[3] = __float_as_uint(qs[(m0 + ar + 8) * QKSTR + kk + ac + 4]);
#pragma unroll
            for (int nt = 0; nt < 8; nt++) {
                uint32_t bf[2];
                int nb = nt * 8 + ar;
                bf[0] = __float_as_uint(ks[nb * QKSTR + kk + ac]);
                bf[1] = __float_as_uint(ks[nb * QKSTR + kk + ac + 4]);
                mma_tf32(acc[nt], af, bf);
            }
        }

        // all warps in group done READING Qs/Ks -> safe to overwrite with Ps
        asm volatile("bar.sync %0, 128;" :: "r"(group + 1) : "memory");

        // ---- bias + register softmax; store P (aliasing Qs/Ks region) ----
        {
            const float* bc = bias_comb
                + (size_t)(h * NW + (b & (NW - 1))) * NTOK * NTOK;
            float m0r = -1e30f, m1r = -1e30f;
#pragma unroll
            for (int nt = 0; nt < 8; nt++) {
                int c0 = nt * 8 + 2 * ac, c1 = c0 + 1;
                acc[nt][0] = (c0 < NTOK) ? acc[nt][0] + bc[br0 * NTOK + c0] : -1e30f;
                acc[nt][1] = (c1 < NTOK) ? acc[nt][1] + bc[br0 * NTOK + c1] : -1e30f;
                acc[nt][2] = (c0 < NTOK) ? acc[nt][2] + bc[br1 * NTOK + c0] : -1e30f;
                acc[nt][3] = (c1 < NTOK) ? acc[nt][3] + bc[br1 * NTOK + c1] : -1e30f;
                m0r = fmaxf(m0r, fmaxf(acc[nt][0], acc[nt][1]));
                m1r = fmaxf(m1r, fmaxf(acc[nt][2], acc[nt][3]));
            }
            m0r = fmaxf(m0r, __shfl_xor_sync(~0u, m0r, 1));
            m0r = fmaxf(m0r, __shfl_xor_sync(~0u, m0r, 2));
            m1r = fmaxf(m1r, __shfl_xor_sync(~0u, m1r, 1));
            m1r = fmaxf(m1r, __shfl_xor_sync(~0u, m1r, 2));
            float s0 = 0.0f, s1 = 0.0f;
#pragma unroll
            for (int nt = 0; nt < 8; nt++) {
                acc[nt][0] = __expf(acc[nt][0] - m0r); s0 += acc[nt][0];
                acc[nt][1] = __expf(acc[nt][1] - m0r); s0 += acc[nt][1];
                acc[nt][2] = __expf(acc[nt][2] - m1r); s1 += acc[nt][2];
                acc[nt][3] = __expf(acc[nt][3] - m1r); s1 += acc[nt][3];
            }
            s0 += __shfl_xor_sync(~0u, s0, 1); s0 += __shfl_xor_sync(~0u, s0, 2);
            s1 += __shfl_xor_sync(~0u, s1, 1); s1 += __shfl_xor_sync(~0u, s1, 2);
            float i0 = __frcp_rn(s0), i1 = __frcp_rn(s1);
            // P cols 0..55 only (cols 56..63 are zero; PV reads K=56)
#pragma unroll
            for (int nt = 0; nt < 7; nt++) {
                int c0 = nt * 8 + 2 * ac;
                *reinterpret_cast<float2*>(&ps[(m0 + ar) * PSTR + c0]) =
                    make_float2(to_tf32(acc[nt][0] * i0), to_tf32(acc[nt][1] * i0));
                *reinterpret_cast<float2*>(&ps[(m0 + ar + 8) * PSTR + c0]) =
                    make_float2(to_tf32(acc[nt][2] * i1), to_tf32(acc[nt][3] * i1));
            }
        }
        __syncwarp();   // P rows read back by same warp only

        // ---- PV: warp rows m0..m0+15 x d 0..31, K = 56 ----
        {
            float po[4][4];
#pragma unroll
            for (int nt = 0; nt < 4; nt++)
#pragma unroll
                for (int e = 0; e < 4; e++) po[nt][e] = 0.0f;
#pragma unroll
            for (int kt = 0; kt < 7; kt++) {
                int kk = kt * 8;
                uint32_t af[4];
                af[0] = __float_as_uint(ps[(m0 + ar) * PSTR + kk + ac]);
                af[1] = __float_as_uint(ps[(m0 + ar + 8) * PSTR + kk + ac]);
                af[2] = __float_as_uint(ps[(m0 + ar) * PSTR + kk + ac + 4]);
                af[3] = __float_as_uint(ps[(m0 + ar + 8) * PSTR + kk + ac + 4]);
#pragma unroll
                for (int nt = 0; nt < 4; nt++) {
                    uint32_t bf[2];
                    int nb = nt * 8 + ar;
                    bf[0] = __float_as_uint(vt[nb * VSTR + kk + ac]);
                    bf[1] = __float_as_uint(vt[nb * VSTR + kk + ac + 4]);
                    mma_tf32(po[nt], af, bf);
                }
            }
            int i0 = m0 + ar;
#pragma unroll
            for (int nt = 0; nt < 4; nt++) {
                int col = hcol + nt * 8 + 2 * ac;
                if (i0 < NTOK)
                    *reinterpret_cast<float2*>(
                        &att_out[(row_base + i0) * DIM + col]) =
                        make_float2(to_tf32(po[nt][0]), to_tf32(po[nt][1]));
                if (i0 + 8 < NTOK)
                    *reinterpret_cast<float2*>(
                        &att_out[(row_base + i0 + 8) * DIM + col]) =
                        make_float2(to_tf32(po[nt][2]), to_tf32(po[nt][3]));
            }
        }

        // protect Vt and Ps before next head's staging
        asm volatile("bar.sync %0, 128;" :: "r"(group + 1) : "memory");
    }
}

// ---------------------------------------------------------------------------
// Launch
// Inputs: 0:x 1:mask 2:qkv_w 3:qkv_b 4:proj_w 5:proj_b 6:rpb_table 7:rel_index
// ---------------------------------------------------------------------------
extern "C" void kernel_launch(void* const* d_in, const int* in_sizes, int n_in,
                              void* d_out, int out_size) {
    const float* x         = (const float*)d_in[0];
    const float* mask      = (const float*)d_in[1];
    const float* qkv_w     = (const float*)d_in[2];
    const float* qkv_b     = (const float*)d_in[3];
    const float* proj_w    = (const float*)d_in[4];
    const float* proj_b    = (const float*)d_in[5];
    const float* rpb_table = (const float*)d_in[6];
    const int*   rel_index = (const int*)d_in[7];
    float* out = (float*)d_out;

    float *qkv, *att, *xr, *wqkv, *wproj, *biasc;
    cudaGetSymbolAddress((void**)&qkv,   g_qkv);
    cudaGetSymbolAddress((void**)&att,   g_att);
    cudaGetSymbolAddress((void**)&xr,    g_xr);
    cudaGetSymbolAddress((void**)&wqkv,  g_wqkv);
    cudaGetSymbolAddress((void**)&wproj, g_wproj);
    cudaGetSymbolAddress((void**)&biasc, g_bias);

    static bool attr_done = false;
    if (!attr_done) {
        cudaFuncSetAttribute(tf32_gemm_bias_kernel,
                             cudaFuncAttributeMaxDynamicSharedMemorySize,
                             GEMM_SMEM);
        cudaFuncSetAttribute(window_attn_mma4_kernel,
                             cudaFuncAttributeMaxDynamicSharedMemorySize,
                             ATT_SMEM);
        attr_done = true;
    }

    // launches 0,1: prep
    {
        int n4 = NX4 + NQ4 + NP4;
        round_all_kernel<<<(n4 + 255) / 256, 256>>>(x, qkv_w, proj_w, xr, wqkv, wproj);
        int nb = NH * NW * NTOK * NTOK;
        bias_comb_kernel<<<(nb + 255) / 256, 256>>>(rpb_table, rel_index, mask, biasc);
    }

    // launch 2: QKV projection (100352,256)@(768,256)^T
    tf32_gemm_bias_kernel<<<dim3(QKV_COLS / GBN, ROWS / GBM), 256, GEMM_SMEM>>>(
        xr, wqkv, qkv_b, qkv, ROWS, QKV_COLS, DIM);

    // launch 3: attention (ncu capture slot)
    window_attn_mma4_kernel<<<NB, 256, ATT_SMEM>>>(qkv, biasc, att);

    // launch 4: output projection (100352,256)@(256,256)^T
    tf32_gemm_bias_kernel<<<dim3(DIM / GBN, ROWS / GBM), 256, GEMM_SMEM>>>(
        att, wproj, proj_b, out, ROWS, DIM, DIM);
}

// round 15
// speedup vs baseline: 1.6485x; 1.0258x over previous
#include <cuda_runtime.h>
#include <cuda_bf16.h>
#include <math.h>
#include <stdint.h>

// ---------------------------------------------------------------------------
// Problem constants
// ---------------------------------------------------------------------------
#define WS   7
#define NTOK 49
#define DIM  256
#define NH   8
#define DH   32
#define NB   2048
#define NW   64
#define ROWS (NB * NTOK)   // 100352
#define QKV_COLS (3 * DIM) // 768

// Scratch (static device globals)
__device__ float g_qkv[(size_t)ROWS * QKV_COLS];
__device__ float g_att[(size_t)ROWS * DIM];
__device__ float g_xr[(size_t)ROWS * DIM];
__device__ float g_wqkv[QKV_COLS * DIM];
__device__ float g_wproj[DIM * DIM];
// padded, pre-masked bias: [h][w][49][64]; cols 49..63 = -1e30
__device__ float g_bias[NH * NW * NTOK * 64];

__device__ __forceinline__ float to_tf32(float x) {
    asm("cvt.rna.tf32.f32 %0, %1;" : "=f"(x) : "f"(x));
    return x;
}

// ---------------------------------------------------------------------------
// Prep kernels
// ---------------------------------------------------------------------------
#define NX4 (ROWS * DIM / 4)
#define NQ4 (QKV_COLS * DIM / 4)
#define NP4 (DIM * DIM / 4)

__global__ void round_all_kernel(const float* __restrict__ x,
                                 const float* __restrict__ qw,
                                 const float* __restrict__ pw,
                                 float* __restrict__ xr,
                                 float* __restrict__ wq,
                                 float* __restrict__ wp) {
    int i = blockIdx.x * blockDim.x + threadIdx.x;
    const float4* src;
    float4* dst;
    int j;
    if (i < NX4)            { src = (const float4*)x;  dst = (float4*)xr; j = i; }
    else if (i < NX4 + NQ4) { src = (const float4*)qw; dst = (float4*)wq; j = i - NX4; }
    else if (i < NX4 + NQ4 + NP4) { src = (const float4*)pw; dst = (float4*)wp; j = i - NX4 - NQ4; }
    else return;
    float4 v = src[j];
    v.x = to_tf32(v.x); v.y = to_tf32(v.y);
    v.z = to_tf32(v.z); v.w = to_tf32(v.w);
    dst[j] = v;
}

// bias_pad[((h*64+w)*49 + r)*64 + c] = rpb+mask (c<49) | -1e30 (c>=49)
__global__ void bias_comb_kernel(const float* __restrict__ rpb_table,
                                 const int* __restrict__ rel_index,
                                 const float* __restrict__ mask,
                                 float* __restrict__ bias) {
    int idx = blockIdx.x * blockDim.x + threadIdx.x;
    const int total = NH * NW * NTOK * 64;
    if (idx >= total) return;
    int c = idx & 63;
    int r = (idx >> 6) % NTOK;
    int w = (idx / (64 * NTOK)) % NW;
    int h = idx / (64 * NTOK * NW);
    float v;
    if (c < NTOK) {
        int p = r * NTOK + c;
        v = rpb_table[rel_index[p] * NH + h] + mask[w * NTOK * NTOK + p];
    } else {
        v = -1e30f;
    }
    bias[idx] = v;
}

// ---------------------------------------------------------------------------
// tf32 tensor-core GEMM — EXACT round-11/14 proven config:
// Block 128x128, BK=32, 8 warps each 64x32, 256 threads, 3-stage cp.async.
// ---------------------------------------------------------------------------
#define GBM 128
#define GBN 128
#define GBK 32
#define TSTR 36
#define ASZ (GBM * TSTR)
#define BSZ (GBN * TSTR)
#define STAGE_FLOATS (ASZ + BSZ)
#define GEMM_SMEM (3 * STAGE_FLOATS * 4)     // 110592 bytes

__device__ __forceinline__ void cp_async16(uint32_t saddr, const void* g) {
    asm volatile("cp.async.cg.shared.global [%0], [%1], 16;\n"
                 :: "r"(saddr), "l"(g));
}
__device__ __forceinline__ void cp_commit() {
    asm volatile("cp.async.commit_group;\n");
}
__device__ __forceinline__ void cp_wait1() {
    asm volatile("cp.async.wait_group 1;\n");
}
__device__ __forceinline__ void cp_wait0() {
    asm volatile("cp.async.wait_group 0;\n");
}

__device__ __forceinline__ void mma_tf32(float d[4], const uint32_t a[4],
                                         const uint32_t b[2]) {
    asm volatile(
        "mma.sync.aligned.m16n8k8.row.col.f32.tf32.tf32.f32 "
        "{%0,%1,%2,%3}, {%4,%5,%6,%7}, {%8,%9}, {%0,%1,%2,%3};\n"
        : "+f"(d[0]), "+f"(d[1]), "+f"(d[2]), "+f"(d[3])
        : "r"(a[0]), "r"(a[1]), "r"(a[2]), "r"(a[3]), "r"(b[0]), "r"(b[1]));
}

__global__ __launch_bounds__(256, 2)
void tf32_gemm_bias_kernel(const float* __restrict__ A,
                           const float* __restrict__ W,
                           const float* __restrict__ bias,
                           float* __restrict__ C,
                           int M, int Nc, int K) {
    extern __shared__ float sm[];

    const int tx = threadIdx.x;
    const int lane = tx & 31;
    const int warp = tx >> 5;
    const int wm = (warp & 1) * 64;
    const int wn = (warp >> 1) * 32;
    const int rowBlk = blockIdx.y * GBM;
    const int colBlk = blockIdx.x * GBN;

    const int lr = tx >> 3;
    const int lc4 = (tx & 7) * 4;

    float acc[4][4][4];
#pragma unroll
    for (int mt = 0; mt < 4; mt++)
#pragma unroll
        for (int nt = 0; nt < 4; nt++)
#pragma unroll
            for (int e = 0; e < 4; e++) acc[mt][nt][e] = 0.0f;

    const int ar = lane >> 2;
    const int ac = lane & 3;
    const int nk = K >> 5;

    auto load_tile = [&](int kt, int buf) {
        float* ad = sm + buf * STAGE_FLOATS;
        float* bd = ad + ASZ;
#pragma unroll
        for (int i = 0; i < 4; i++) {
            int r = lr + i * 32;
            cp_async16((uint32_t)__cvta_generic_to_shared(ad + r * TSTR + lc4),
                       &A[(size_t)(rowBlk + r) * K + (kt << 5) + lc4]);
            cp_async16((uint32_t)__cvta_generic_to_shared(bd + r * TSTR + lc4),
                       &W[(size_t)(colBlk + r) * K + (kt << 5) + lc4]);
        }
        cp_commit();
    };

    load_tile(0, 0);
    if (nk > 1) load_tile(1, 1);

    int buf = 0;
    for (int t = 0; t < nk; t++) {
        if (t + 1 < nk) cp_wait1();
        else            cp_wait0();
        __syncthreads();
        if (t + 2 < nk) {
            int nb = buf + 2; if (nb >= 3) nb -= 3;
            load_tile(t + 2, nb);
        }

        const float* a = sm + buf * STAGE_FLOATS;
        const float* b = a + ASZ;
#pragma unroll
        for (int kk = 0; kk < GBK; kk += 8) {
            uint32_t af[4][4];
#pragma unroll
            for (int mt = 0; mt < 4; mt++) {
                int mb = wm + mt * 16;
                af[mt][0] = __float_as_uint(a[(mb + ar) * TSTR + kk + ac]);
                af[mt][1] = __float_as_uint(a[(mb + ar + 8) * TSTR + kk + ac]);
                af[mt][2] = __float_as_uint(a[(mb + ar) * TSTR + kk + ac + 4]);
                af[mt][3] = __float_as_uint(a[(mb + ar + 8) * TSTR + kk + ac + 4]);
            }
            uint32_t bf[4][2];
#pragma unroll
            for (int nt = 0; nt < 4; nt++) {
                int nb2 = wn + nt * 8 + ar;
                bf[nt][0] = __float_as_uint(b[nb2 * TSTR + kk + ac]);
                bf[nt][1] = __float_as_uint(b[nb2 * TSTR + kk + ac + 4]);
            }
#pragma unroll
            for (int mt = 0; mt < 4; mt++)
#pragma unroll
                for (int nt = 0; nt < 4; nt++)
                    mma_tf32(acc[mt][nt], af[mt], bf[nt]);
        }
        if (++buf >= 3) buf = 0;
    }

    const int cr = lane >> 2;
    const int cc = (lane & 3) * 2;
#pragma unroll
    for (int mt = 0; mt < 4; mt++) {
#pragma unroll
        for (int nt = 0; nt < 4; nt++) {
            int row = rowBlk + wm + mt * 16 + cr;
            int col = colBlk + wn + nt * 8 + cc;
            float b0 = bias[col], b1 = bias[col + 1];
            float2 v0 = make_float2(acc[mt][nt][0] + b0, acc[mt][nt][1] + b1);
            float2 v1 = make_float2(acc[mt][nt][2] + b0, acc[mt][nt][3] + b1);
            *reinterpret_cast<float2*>(&C[(size_t)row * Nc + col]) = v0;
            *reinterpret_cast<float2*>(&C[(size_t)(row + 8) * Nc + col]) = v1;
        }
    }
}

// ---------------------------------------------------------------------------
// Tensor-core window attention v5. CTA = 128 threads (one 4-warp group),
// grid (NB, 2): CTA (b, g) handles heads {g, g+2, g+4, g+6} of window b.
//   - smem 27.1KB/CTA -> 8 CTAs/SM (was 2x256-thread at 54KB -> 4)
//   - Ps aliases Qs/Ks (extra syncthreads between QK-read and P-write)
//   - bias pre-masked & padded to 64 cols -> branchless float2 adds
//   - Q/K staged via float4 STS
// ---------------------------------------------------------------------------
#define QKSTR 36
#define PSTR  60
#define VSTR  68
#define VT_OFF 0
#define QS_OFF (DH * VSTR)                   // 2176
#define KS_OFF (QS_OFF + 64 * QKSTR)         // 4480
#define PS_OFF QS_OFF                        // alias Qs (+start of Ks)
#define GRP_FLOATS (QS_OFF + 2 * 64 * QKSTR) // 6784 floats = 27136 B

__global__ __launch_bounds__(128, 8)
void window_attn_mma5_kernel(const float* __restrict__ qkv,
                             const float* __restrict__ bias_pad,
                             float* __restrict__ att_out) {
    __shared__ float smf[GRP_FLOATS];

    const int b = blockIdx.x;
    const int group = blockIdx.y;         // 0 or 1
    const int tid = threadIdx.x;          // 0..127
    const int lane = tid & 31;
    const int wg = tid >> 5;              // warp 0..3
    const int ar = lane >> 2;
    const int ac = lane & 3;
    const int m0 = wg * 16;
    const size_t row_base = (size_t)b * NTOK;
    const float scale = 0.17677669529663687f;

    float* vt = smf + VT_OFF;
    float* qs = smf + QS_OFF;
    float* ks = smf + KS_OFF;
    float* ps = smf + PS_OFF;

    const int br0 = (m0 + ar < NTOK) ? m0 + ar : NTOK - 1;
    const int br1 = (m0 + ar + 8 < NTOK) ? m0 + ar + 8 : NTOK - 1;

    for (int hh = 0; hh < 4; hh++) {
        const int h = hh * 2 + group;
        const int hcol = h * DH;

        // ---- stage Q (scaled, tf32), K; pad rows zeroed (Ps aliased) ----
        for (int p = tid; p < 64 * 8; p += 128) {
            int n = p >> 3, d0 = (p & 7) * 4;
            float4 q, k;
            if (n < NTOK) {
                const float* base = qkv + (row_base + n) * QKV_COLS + hcol + d0;
                q = *reinterpret_cast<const float4*>(base);
                k = *reinterpret_cast<const float4*>(base + DIM);
                q.x *= scale; q.y *= scale; q.z *= scale; q.w *= scale;
            } else {
                q = make_float4(0.f, 0.f, 0.f, 0.f);
                k = q;
            }
            float4 qr = make_float4(to_tf32(q.x), to_tf32(q.y),
                                    to_tf32(q.z), to_tf32(q.w));
            float4 kr = make_float4(to_tf32(k.x), to_tf32(k.y),
                                    to_tf32(k.z), to_tf32(k.w));
            *reinterpret_cast<float4*>(&qs[n * QKSTR + d0]) = qr;   // 144B rows: 16B aligned
            *reinterpret_cast<float4*>(&ks[n * QKSTR + d0]) = kr;
        }
        // ---- V^T staging: vt[d][j], j pads zeroed ----
#pragma unroll
        for (int jj = 0; jj < 14; jj++) {
            int j = wg * 14 + jj;          // 0..55
            float v = (j < NTOK)
                ? qkv[(row_base + j) * QKV_COLS + hcol + 2 * DIM + lane] : 0.0f;
            vt[lane * VSTR + j] = to_tf32(v);
        }
        __syncthreads();

        // ---- QK^T: warp rows m0..m0+15 x cols 0..63 ----
        float acc[8][4];
#pragma unroll
        for (int nt = 0; nt < 8; nt++)
#pragma unroll
            for (int e = 0; e < 4; e++) acc[nt][e] = 0.0f;
#pragma unroll
        for (int kt = 0; kt < 4; kt++) {
            int kk = kt * 8;
            uint32_t af[4];
            af[0] = __float_as_uint(qs[(m0 + ar) * QKSTR + kk + ac]);
            af[1] = __float_as_uint(qs[(m0 + ar + 8) * QKSTR + kk + ac]);
            af[2] = __float_as_uint(qs[(m0 + ar) * QKSTR + kk + ac + 4]);
            af[3] = __float_as_uint(qs[(m0 + ar + 8) * QKSTR + kk + ac + 4]);
#pragma unroll
            for (int nt = 0; nt < 8; nt++) {
                uint32_t bf[2];
                int nb = nt * 8 + ar;
                bf[0] = __float_as_uint(ks[nb * QKSTR + kk + ac]);
                bf[1] = __float_as_uint(ks[nb * QKSTR + kk + ac + 4]);
                mma_tf32(acc[nt], af, bf);
            }
        }

        // all warps done READING Qs/Ks -> safe to overwrite with Ps
        __syncthreads();

        // ---- bias (pre-masked, padded) + register softmax; store P ----
        {
            const float* bc = bias_pad
                + (size_t)((h * NW + (b & (NW - 1))) * NTOK) * 64;
            float m0r = -1e30f, m1r = -1e30f;
#pragma unroll
            for (int nt = 0; nt < 8; nt++) {
                int c0 = nt * 8 + 2 * ac;
                float2 b0 = *reinterpret_cast<const float2*>(&bc[br0 * 64 + c0]);
                float2 b1 = *reinterpret_cast<const float2*>(&bc[br1 * 64 + c0]);
                acc[nt][0] += b0.x;
                acc[nt][1] += b0.y;
                acc[nt][2] += b1.x;
                acc[nt][3] += b1.y;
                m0r = fmaxf(m0r, fmaxf(acc[nt][0], acc[nt][1]));
                m1r = fmaxf(m1r, fmaxf(acc[nt][2], acc[nt][3]));
            }
            m0r = fmaxf(m0r, __shfl_xor_sync(~0u, m0r, 1));
            m0r = fmaxf(m0r, __shfl_xor_sync(~0u, m0r, 2));
            m1r = fmaxf(m1r, __shfl_xor_sync(~0u, m1r, 1));
            m1r = fmaxf(m1r, __shfl_xor_sync(~0u, m1r, 2));
            float s0 = 0.0f, s1 = 0.0f;
#pragma unroll
            for (int nt = 0; nt < 8; nt++) {
                acc[nt][0] = __expf(acc[nt][0] - m0r); s0 += acc[nt][0];
                acc[nt][1] = __expf(acc[nt][1] - m0r); s0 += acc[nt][1];
                acc[nt][2] = __expf(acc[nt][2] - m1r); s1 += acc[nt][2];
                acc[nt][3] = __expf(acc[nt][3] - m1r); s1 += acc[nt][3];
            }
            s0 += __shfl_xor_sync(~0u, s0, 1); s0 += __shfl_xor_sync(~0u, s0, 2);
            s1 += __shfl_xor_sync(~0u, s1, 1); s1 += __shfl_xor_sync(~0u, s1, 2);
            float i0 = __frcp_rn(s0), i1 = __frcp_rn(s1);
            // P cols 0..55 only (cols 56..63 are zero; PV reads K=56)
#pragma unroll
            for (int nt = 0; nt < 7; nt++) {
                int c0 = nt * 8 + 2 * ac;
                *reinterpret_cast<float2*>(&ps[(m0 + ar) * PSTR + c0]) =
                    make_float2(to_tf32(acc[nt][0] * i0), to_tf32(acc[nt][1] * i0));
                *reinterpret_cast<float2*>(&ps[(m0 + ar + 8) * PSTR + c0]) =
                    make_float2(to_tf32(acc[nt][2] * i1), to_tf32(acc[nt][3] * i1));
            }
        }
        __syncwarp();   // P rows read back by same warp only

        // ---- PV: warp rows m0..m0+15 x d 0..31, K = 56 ----
        {
            float po[4][4];
#pragma unroll
            for (int nt = 0; nt < 4; nt++)
#pragma unroll
                for (int e = 0; e < 4; e++) po[nt][e] = 0.0f;
#pragma unroll
            for (int kt = 0; kt < 7; kt++) {
                int kk = kt * 8;
                uint32_t af[4];
                af[0] = __float_as_uint(ps[(m0 + ar) * PSTR + kk + ac]);
                af[1] = __float_as_uint(ps[(m0 + ar + 8) * PSTR + kk + ac]);
                af[2] = __float_as_uint(ps[(m0 + ar) * PSTR + kk + ac + 4]);
                af[3] = __float_as_uint(ps[(m0 + ar + 8) * PSTR + kk + ac + 4]);
#pragma unroll
                for (int nt = 0; nt < 4; nt++) {
                    uint32_t bf[2];
                    int nb = nt * 8 + ar;
                    bf[0] = __float_as_uint(vt[nb * VSTR + kk + ac]);
                    bf[1] = __float_as_uint(vt[nb * VSTR + kk + ac + 4]);
                    mma_tf32(po[nt], af, bf);
                }
            }
            int i0 = m0 + ar;
#pragma unroll
            for (int nt = 0; nt < 4; nt++) {
                int col = hcol + nt * 8 + 2 * ac;
                if (i0 < NTOK)
                    *reinterpret_cast<float2*>(
                        &att_out[(row_base + i0) * DIM + col]) =
                        make_float2(to_tf32(po[nt][0]), to_tf32(po[nt][1]));
                if (i0 + 8 < NTOK)
                    *reinterpret_cast<float2*>(
                        &att_out[(row_base + i0 + 8) * DIM + col]) =
                        make_float2(to_tf32(po[nt][2]), to_tf32(po[nt][3]));
            }
        }

        // protect Vt and Ps before next head's staging
        __syncthreads();
    }
}

// ---------------------------------------------------------------------------
// Launch
// Inputs: 0:x 1:mask 2:qkv_w 3:qkv_b 4:proj_w 5:proj_b 6:rpb_table 7:rel_index
// ---------------------------------------------------------------------------
extern "C" void kernel_launch(void* const* d_in, const int* in_sizes, int n_in,
                              void* d_out, int out_size) {
    const float* x         = (const float*)d_in[0];
    const float* mask      = (const float*)d_in[1];
    const float* qkv_w     = (const float*)d_in[2];
    const float* qkv_b     = (const float*)d_in[3];
    const float* proj_w    = (const float*)d_in[4];
    const float* proj_b    = (const float*)d_in[5];
    const float* rpb_table = (const float*)d_in[6];
    const int*   rel_index = (const int*)d_in[7];
    float* out = (float*)d_out;

    float *qkv, *att, *xr, *wqkv, *wproj, *biasc;
    cudaGetSymbolAddress((void**)&qkv,   g_qkv);
    cudaGetSymbolAddress((void**)&att,   g_att);
    cudaGetSymbolAddress((void**)&xr,    g_xr);
    cudaGetSymbolAddress((void**)&wqkv,  g_wqkv);
    cudaGetSymbolAddress((void**)&wproj, g_wproj);
    cudaGetSymbolAddress((void**)&biasc, g_bias);

    static bool attr_done = false;
    if (!attr_done) {
        cudaFuncSetAttribute(tf32_gemm_bias_kernel,
                             cudaFuncAttributeMaxDynamicSharedMemorySize,
                             GEMM_SMEM);
        attr_done = true;
    }

    // launches 0,1: prep
    {
        int n4 = NX4 + NQ4 + NP4;
        round_all_kernel<<<(n4 + 255) / 256, 256>>>(x, qkv_w, proj_w, xr, wqkv, wproj);
        int nb = NH * NW * NTOK * 64;
        bias_comb_kernel<<<(nb + 255) / 256, 256>>>(rpb_table, rel_index, mask, biasc);
    }

    // launch 2: QKV projection (100352,256)@(768,256)^T
    tf32_gemm_bias_kernel<<<dim3(QKV_COLS / GBN, ROWS / GBM), 256, GEMM_SMEM>>>(
        xr, wqkv, qkv_b, qkv, ROWS, QKV_COLS, DIM);

    // launch 3: attention — (window, head-group) grid, 128-thread CTAs
    window_attn_mma5_kernel<<<dim3(NB, 2), 128>>>(qkv, biasc, att);

    // launch 4: output projection (100352,256)@(256,256)^T
    tf32_gemm_bias_kernel<<<dim3(DIM / GBN, ROWS / GBM), 256, GEMM_SMEM>>>(
        att, wproj, proj_b, out, ROWS, DIM, DIM);
}